// round 10
// baseline (speedup 1.0000x reference)
#include <cuda_runtime.h>
#include <cuda_bf16.h>
#include <cstdint>

// GDLoss: elementwise Gaussian KL loss over [N,5] xywhr boxes. 176MB traffic.
// R10: NO shared memory, NO barriers. 4 boxes/thread = exactly 5 aligned
// float4 per tensor -> 10 independent LDG.128 per thread (MLP=10), 4 losses,
// 1 STG.128. R5-R9 pipelines all plateaued at ~30.5us / DRAM~70% with nothing
// saturated; this removes every sync point and all smem traffic. DRAM traffic
// identical (all lines fully consumed); cost shifts to L1 wavefronts (~23us
// model), below the observed plateau.

#define TAU_F   1.0f
#define EPS_F   1e-6f
#define BLK     256

__device__ __forceinline__ float rcp_fast(float x) {
    float r; asm("rcp.approx.f32 %0, %1;" : "=f"(r) : "f"(x)); return r;
}
__device__ __forceinline__ float sqrt_fast(float x) {
    float r; asm("sqrt.approx.f32 %0, %1;" : "=f"(r) : "f"(x)); return r;
}

// loss for one box pair:
//   det_t = tww*thh/16, det_p = pww*phh/16     (rotation-invariant, no trig)
//   t1num = ths(dx^2+dy^2) - thd(c2t(dx^2-dy^2) + 2 s2t dx dy)
//   n2num = 2(ths*phs - thd*phd*cos(2rt-2rp))
//   dis   = (t1num+n2num)*16/(tww*thh) + log((tww*thh)/(pww*phh)) - 2
__device__ __forceinline__ float gd_loss_one(
    float px, float py, float pw, float ph, float prr,
    float tx, float ty, float tw, float th, float trr)
{
    pw = fminf(fmaxf(pw, 1e-7f), 1e7f);
    ph = fminf(fmaxf(ph, 1e-7f), 1e7f);
    tw = fminf(fmaxf(tw, 1e-7f), 1e7f);
    th = fminf(fmaxf(th, 1e-7f), 1e7f);

    const float pww = pw * pw, phh = ph * ph;
    const float tww = tw * tw, thh = th * th;

    const float phs = 0.125f * (pww + phh);
    const float phd = 0.125f * (pww - phh);
    const float ths = 0.125f * (tww + thh);
    const float thd = 0.125f * (tww - thh);

    float s2t, c2t;
    __sincosf(2.0f * trr, &s2t, &c2t);
    const float cdd = __cosf(2.0f * (trr - prr));   // cos(2rt - 2rp)

    const float dx = px - tx;
    const float dy = py - ty;
    const float dx2 = dx * dx, dy2 = dy * dy;
    const float sum2 = dx2 + dy2, dif2 = dx2 - dy2;
    const float dxy = dx * dy;

    const float rot   = fmaf(c2t, dif2, 2.0f * s2t * dxy);
    const float t1num = fmaf(ths, sum2, -thd * rot);
    const float n2num = 2.0f * fmaf(-thd * phd, cdd, ths * phs);

    const float dtt = tww * thh;                    // 16*det_t
    const float dpp = pww * phh;                    // 16*det_p
    const float invdt16 = 16.0f * rcp_fast(dtt);
    const float logterm = __logf(dtt * rcp_fast(dpp));

    const float dis = fmaf(t1num + n2num, invdt16, logterm - 2.0f);
    const float kl = fmaxf(dis, EPS_F);
    return 1.0f - rcp_fast(TAU_F + sqrt_fast(kl));
}

__global__ void __launch_bounds__(BLK) gd_loss_kernel(
    const float* __restrict__ pred,
    const float* __restrict__ target,
    float* __restrict__ out,
    int n)
{
    const int q = blockIdx.x * BLK + threadIdx.x;   // quad index (4 boxes)
    const int b0 = q * 4;                            // first box of this quad
    if (b0 >= n) return;

    if (b0 + 3 < n) {
        // Fast path: 4 boxes = 5 float4 per tensor, all independent LDG.128.
        const float4* __restrict__ p4 = (const float4*)pred + (size_t)q * 5;
        const float4* __restrict__ t4 = (const float4*)target + (size_t)q * 5;

        float4 a0, a1, a2, a3, a4, c0, c1, c2, c3, c4;
        a0 = p4[0]; a1 = p4[1]; a2 = p4[2]; a3 = p4[3]; a4 = p4[4];
        c0 = t4[0]; c1 = t4[1]; c2 = t4[2]; c3 = t4[3]; c4 = t4[4];

        float4 res;
        // box 0: f[0..4]
        res.x = gd_loss_one(a0.x, a0.y, a0.z, a0.w, a1.x,
                            c0.x, c0.y, c0.z, c0.w, c1.x);
        // box 1: f[5..9]
        res.y = gd_loss_one(a1.y, a1.z, a1.w, a2.x, a2.y,
                            c1.y, c1.z, c1.w, c2.x, c2.y);
        // box 2: f[10..14]
        res.z = gd_loss_one(a2.z, a2.w, a3.x, a3.y, a3.z,
                            c2.z, c2.w, c3.x, c3.y, c3.z);
        // box 3: f[15..19]
        res.w = gd_loss_one(a3.w, a4.x, a4.y, a4.z, a4.w,
                            c3.w, c4.x, c4.y, c4.z, c4.w);

        *(float4*)(out + b0) = res;
    } else {
        // Tail quad: scalar per box.
        for (int b = b0; b < n; ++b) {
            const float* p = pred + (size_t)b * 5;
            const float* t = target + (size_t)b * 5;
            out[b] = gd_loss_one(p[0], p[1], p[2], p[3], p[4],
                                 t[0], t[1], t[2], t[3], t[4]);
        }
    }
}

extern "C" void kernel_launch(void* const* d_in, const int* in_sizes, int n_in,
                              void* d_out, int out_size)
{
    const float* pred   = (const float*)d_in[0];
    const float* target = (const float*)d_in[1];
    // d_in[2] (weight) is unused by the reference computation (LOSS_WEIGHT=1).
    float* out = (float*)d_out;

    const int n = out_size;                       // N boxes; output is [N,1] floats
    const int quads = (n + 3) / 4;                // 1M for N=4M
    const int grid = (quads + BLK - 1) / BLK;     // 3907
    gd_loss_kernel<<<grid, BLK>>>(pred, target, out, n);
}

// round 11
// speedup vs baseline: 1.1967x; 1.1967x over previous
#include <cuda_runtime.h>
#include <cuda_bf16.h>
#include <cstdint>

// GDLoss: elementwise Gaussian KL loss over [N,5] xywhr boxes. 176MB traffic.
// R11: per-warp autonomous cp.async pipelines - ZERO block barriers.
// Each warp owns a private 3-stage ring (32-box tiles) and streams
// independently: cp.async.wait_group + __syncwarp only. Removes the per-tile
// block-wide __syncthreads lockstep that (theory) punched duty-cycle holes in
// the memory stream and pinned R5-R9 at ~30us / DRAM ~70%.

#define TAU_F   1.0f
#define EPS_F   1e-6f
#define BLK     256
#define NW      (BLK / 32)           // 8 warps
#define STAGES  3
#define WTILE   32                   // boxes per warp-tile
#define WTF     (WTILE * 5)          // 160 floats per tensor per warp-tile
#define WTV4    (WTF / 4)            // 40 float4 per tensor per warp-tile
#define GRID_P  1064                 // 7 blocks/SM * 152 SMs

__device__ __forceinline__ void cp_async16(unsigned smem_dst, const void* gmem_src) {
    asm volatile("cp.async.cg.shared.global [%0], [%1], 16;\n"
                 :: "r"(smem_dst), "l"(gmem_src));
}
__device__ __forceinline__ void cp_async4(unsigned smem_dst, const void* gmem_src) {
    asm volatile("cp.async.ca.shared.global [%0], [%1], 4;\n"
                 :: "r"(smem_dst), "l"(gmem_src));
}
__device__ __forceinline__ void cp_commit() {
    asm volatile("cp.async.commit_group;\n" ::: "memory");
}
template <int N>
__device__ __forceinline__ void cp_wait() {
    asm volatile("cp.async.wait_group %0;\n" :: "n"(N) : "memory");
}

__device__ __forceinline__ float rcp_fast(float x) {
    float r; asm("rcp.approx.f32 %0, %1;" : "=f"(r) : "f"(x)); return r;
}
__device__ __forceinline__ float sqrt_fast(float x) {
    float r; asm("sqrt.approx.f32 %0, %1;" : "=f"(r) : "f"(x)); return r;
}

// loss for one box pair (algebraically reduced):
//   det_t = tww*thh/16, det_p = pww*phh/16     (rotation-invariant, no trig)
//   t1num = ths(dx^2+dy^2) - thd(c2t(dx^2-dy^2) + 2 s2t dx dy)
//   n2num = 2(ths*phs - thd*phd*cos(2rt-2rp))
//   dis   = (t1num+n2num)*16/(tww*thh) + log((tww*thh)/(pww*phh)) - 2
__device__ __forceinline__ float gd_loss_one(
    float px, float py, float pw, float ph, float prr,
    float tx, float ty, float tw, float th, float trr)
{
    pw = fminf(fmaxf(pw, 1e-7f), 1e7f);
    ph = fminf(fmaxf(ph, 1e-7f), 1e7f);
    tw = fminf(fmaxf(tw, 1e-7f), 1e7f);
    th = fminf(fmaxf(th, 1e-7f), 1e7f);

    const float pww = pw * pw, phh = ph * ph;
    const float tww = tw * tw, thh = th * th;

    const float phs = 0.125f * (pww + phh);
    const float phd = 0.125f * (pww - phh);
    const float ths = 0.125f * (tww + thh);
    const float thd = 0.125f * (tww - thh);

    float s2t, c2t;
    __sincosf(2.0f * trr, &s2t, &c2t);
    const float cdd = __cosf(2.0f * (trr - prr));   // cos(2rt - 2rp)

    const float dx = px - tx;
    const float dy = py - ty;
    const float dx2 = dx * dx, dy2 = dy * dy;
    const float sum2 = dx2 + dy2, dif2 = dx2 - dy2;
    const float dxy = dx * dy;

    const float rot   = fmaf(c2t, dif2, 2.0f * s2t * dxy);
    const float t1num = fmaf(ths, sum2, -thd * rot);
    const float n2num = 2.0f * fmaf(-thd * phd, cdd, ths * phs);

    const float dtt = tww * thh;                    // 16*det_t
    const float dpp = pww * phh;                    // 16*det_p
    const float invdt16 = 16.0f * rcp_fast(dtt);
    const float logterm = __logf(dtt * rcp_fast(dpp));

    const float dis = fmaf(t1num + n2num, invdt16, logterm - 2.0f);
    const float kl = fmaxf(dis, EPS_F);
    return 1.0f - rcp_fast(TAU_F + sqrt_fast(kl));
}

__global__ void __launch_bounds__(BLK) gd_loss_kernel(
    const float* __restrict__ pred,
    const float* __restrict__ target,
    float* __restrict__ out,
    int n)
{
    // [warp][stage][tensor 0=pred 1=target][160 floats]
    __shared__ float sbuf[NW][STAGES][2][WTF];

    const int lane = threadIdx.x & 31;
    const int wid  = threadIdx.x >> 5;

    const int numTiles = (n + WTILE - 1) / WTILE;   // 125000 for N=4M
    const int wstride  = gridDim.x * NW;            // warp-streams total
    const int wstart   = blockIdx.x * NW + wid;     // this warp's first tile

    // Issue this warp's cp.asyncs for tile t into ring slot. Always commits.
    auto issue = [&](int t, int slot) {
        if (t < numTiles) {
            const int tileBase = t * WTILE;
            const int nb = n - tileBase;
            float* spb = sbuf[wid][slot][0];
            float* stb = sbuf[wid][slot][1];
            const float* pbase = pred   + tileBase * 5;   // <=20M: int32-safe
            const float* tbase = target + tileBase * 5;
            if (nb >= WTILE) {
                // 40 float4 per tensor: lanes 0..31 take i=lane, lanes 0..7 also i=lane+32
                const float4* p4 = (const float4*)pbase;
                const float4* t4 = (const float4*)tbase;
                cp_async16((unsigned)__cvta_generic_to_shared(((float4*)spb) + lane), p4 + lane);
                cp_async16((unsigned)__cvta_generic_to_shared(((float4*)stb) + lane), t4 + lane);
                if (lane < WTV4 - 32) {
                    const int i = lane + 32;
                    cp_async16((unsigned)__cvta_generic_to_shared(((float4*)spb) + i), p4 + i);
                    cp_async16((unsigned)__cvta_generic_to_shared(((float4*)stb) + i), t4 + i);
                }
            } else {
                const int nfloats = nb * 5;
                for (int i = lane; i < nfloats; i += 32) {
                    cp_async4((unsigned)__cvta_generic_to_shared(spb + i), pbase + i);
                    cp_async4((unsigned)__cvta_generic_to_shared(stb + i), tbase + i);
                }
            }
        }
        cp_commit();
    };

    // Prologue: two warp-tiles in flight.
    issue(wstart, 0);
    issue(wstart + wstride, 1);

    int slot = 0;
    for (int tile = wstart; tile < numTiles; tile += wstride) {
        cp_wait<1>();        // this tile's copies landed (next still in flight)
        __syncwarp();        // all lanes: copies visible + compute(k-1) done
        int islot = slot + 2; if (islot >= STAGES) islot -= STAGES;   // slot-1 mod 3
        issue(tile + 2 * wstride, islot);

        const int tileBase = tile * WTILE;
        const int nb = n - tileBase;

        if (lane < nb) {
            const float* spb = sbuf[wid][slot][0];
            const float* stb = sbuf[wid][slot][1];
            const int b5 = lane * 5;  // stride-5 smem: gcd(5,32)=1, conflict-free
            const float loss = gd_loss_one(
                spb[b5 + 0], spb[b5 + 1], spb[b5 + 2], spb[b5 + 3], spb[b5 + 4],
                stb[b5 + 0], stb[b5 + 1], stb[b5 + 2], stb[b5 + 3], stb[b5 + 4]);
            __stcs(out + tileBase + lane, loss);
        }

        ++slot; if (slot >= STAGES) slot = 0;
    }
}

extern "C" void kernel_launch(void* const* d_in, const int* in_sizes, int n_in,
                              void* d_out, int out_size)
{
    const float* pred   = (const float*)d_in[0];
    const float* target = (const float*)d_in[1];
    // d_in[2] (weight) is unused by the reference computation (LOSS_WEIGHT=1).
    float* out = (float*)d_out;

    const int n = out_size;                        // N boxes; output [N,1] floats
    const int numTiles = (n + WTILE - 1) / WTILE;  // 125000 for N=4M
    int grid = GRID_P;
    const int maxGrid = (numTiles + NW - 1) / NW;
    if (grid > maxGrid) grid = maxGrid;
    gd_loss_kernel<<<grid, BLK>>>(pred, target, out, n);
}

// round 12
// speedup vs baseline: 1.1979x; 1.0010x over previous
#include <cuda_runtime.h>
#include <cuda_bf16.h>
#include <cstdint>

// GDLoss: elementwise Gaussian KL loss over [N,5] xywhr boxes. 176MB traffic.
// R12 = R11 (per-warp autonomous 3-stage cp.async rings, zero block barriers;
// best: 29.0us kernel, DRAM 73.5%) + ALU-overhead removal:
//   - manual 3x unroll -> compile-time ring slots, immediate smem offsets
//   - pointer strength reduction for issue/output (no per-iter tile*5 IMADs)
//   - hoisted lane offsets / one cvta per warp
// R11 profile: ALU 31.1% was the top pipe (loop bookkeeping on 32-box tiles).

#define TAU_F   1.0f
#define EPS_F   1e-6f
#define BLK     256
#define NW      (BLK / 32)           // 8 warps
#define STAGES  3
#define WTILE   32                   // boxes per warp-tile
#define WTF     (WTILE * 5)          // 160 floats per tensor per warp-tile
#define GRID_P  1064                 // 7 blocks/SM * 152 SMs

__device__ __forceinline__ void cp_async16(unsigned smem_dst, const void* gmem_src) {
    asm volatile("cp.async.cg.shared.global [%0], [%1], 16;\n"
                 :: "r"(smem_dst), "l"(gmem_src));
}
__device__ __forceinline__ void cp_async4(unsigned smem_dst, const void* gmem_src) {
    asm volatile("cp.async.ca.shared.global [%0], [%1], 4;\n"
                 :: "r"(smem_dst), "l"(gmem_src));
}
__device__ __forceinline__ void cp_commit() {
    asm volatile("cp.async.commit_group;\n" ::: "memory");
}
template <int N>
__device__ __forceinline__ void cp_wait() {
    asm volatile("cp.async.wait_group %0;\n" :: "n"(N) : "memory");
}

__device__ __forceinline__ float rcp_fast(float x) {
    float r; asm("rcp.approx.f32 %0, %1;" : "=f"(r) : "f"(x)); return r;
}
__device__ __forceinline__ float sqrt_fast(float x) {
    float r; asm("sqrt.approx.f32 %0, %1;" : "=f"(r) : "f"(x)); return r;
}

// loss for one box pair (algebraically reduced):
//   det_t = tww*thh/16, det_p = pww*phh/16     (rotation-invariant, no trig)
//   t1num = ths(dx^2+dy^2) - thd(c2t(dx^2-dy^2) + 2 s2t dx dy)
//   n2num = 2(ths*phs - thd*phd*cos(2rt-2rp))
//   dis   = (t1num+n2num)*16/(tww*thh) + log((tww*thh)/(pww*phh)) - 2
__device__ __forceinline__ float gd_loss_one(
    float px, float py, float pw, float ph, float prr,
    float tx, float ty, float tw, float th, float trr)
{
    pw = fminf(fmaxf(pw, 1e-7f), 1e7f);
    ph = fminf(fmaxf(ph, 1e-7f), 1e7f);
    tw = fminf(fmaxf(tw, 1e-7f), 1e7f);
    th = fminf(fmaxf(th, 1e-7f), 1e7f);

    const float pww = pw * pw, phh = ph * ph;
    const float tww = tw * tw, thh = th * th;

    const float phs = 0.125f * (pww + phh);
    const float phd = 0.125f * (pww - phh);
    const float ths = 0.125f * (tww + thh);
    const float thd = 0.125f * (tww - thh);

    float s2t, c2t;
    __sincosf(2.0f * trr, &s2t, &c2t);
    const float cdd = __cosf(2.0f * (trr - prr));   // cos(2rt - 2rp)

    const float dx = px - tx;
    const float dy = py - ty;
    const float dx2 = dx * dx, dy2 = dy * dy;
    const float sum2 = dx2 + dy2, dif2 = dx2 - dy2;
    const float dxy = dx * dy;

    const float rot   = fmaf(c2t, dif2, 2.0f * s2t * dxy);
    const float t1num = fmaf(ths, sum2, -thd * rot);
    const float n2num = 2.0f * fmaf(-thd * phd, cdd, ths * phs);

    const float dtt = tww * thh;                    // 16*det_t
    const float dpp = pww * phh;                    // 16*det_p
    const float invdt16 = 16.0f * rcp_fast(dtt);
    const float logterm = __logf(dtt * rcp_fast(dpp));

    const float dis = fmaf(t1num + n2num, invdt16, logterm - 2.0f);
    const float kl = fmaxf(dis, EPS_F);
    return 1.0f - rcp_fast(TAU_F + sqrt_fast(kl));
}

__global__ void __launch_bounds__(BLK) gd_loss_kernel(
    const float* __restrict__ pred,
    const float* __restrict__ target,
    float* __restrict__ out,
    int n)
{
    // [warp][stage][tensor 0=pred 1=target][160 floats]
    __shared__ float sbuf[NW][STAGES][2][WTF];

    const int lane = threadIdx.x & 31;
    const int wid  = threadIdx.x >> 5;
    const int b5   = lane * 5;

    const int numTiles = (n + WTILE - 1) / WTILE;
    const int wstride  = gridDim.x * NW;
    const int wstart   = blockIdx.x * NW + wid;
    if (wstart >= numTiles) return;

    // Per-warp smem base (shared-space address), one cvta total.
    const unsigned sbase = (unsigned)__cvta_generic_to_shared(&sbuf[wid][0][0][0]);
    const unsigned lane16 = (unsigned)lane * 16u;

    // Issue-side carried state: tile index + gmem pointers, strength-reduced.
    int iTile = wstart;
    const float4* ipp4 = (const float4*)pred   + (size_t)wstart * (WTF / 4);
    const float4* ipt4 = (const float4*)target + (size_t)wstart * (WTF / 4);
    const int ptrStep = wstride * (WTF / 4);     // float4s per issue step

    // ISSUE(SLOT): cp.async this warp's tile `iTile` into compile-time SLOT.
    // Always commits one group; advances carried state.
#define ISSUE(SLOT) do {                                                      \
    if (iTile < numTiles) {                                                   \
        const int inb = n - iTile * WTILE;                                    \
        const unsigned dsp = sbase + (unsigned)((SLOT) * (2 * WTF * 4));      \
        const unsigned dst_ = dsp + (unsigned)(WTF * 4);                      \
        if (inb >= WTILE) {                                                   \
            cp_async16(dsp + lane16, ipp4 + lane);                            \
            cp_async16(dst_ + lane16, ipt4 + lane);                           \
            if (lane < 8) {                                                   \
                cp_async16(dsp + lane16 + 512u, ipp4 + lane + 32);            \
                cp_async16(dst_ + lane16 + 512u, ipt4 + lane + 32);           \
            }                                                                 \
        } else {                                                              \
            const float* pb = (const float*)ipp4;                             \
            const float* tb = (const float*)ipt4;                             \
            const int nf = inb * 5;                                           \
            for (int i = lane; i < nf; i += 32) {                             \
                cp_async4(dsp + (unsigned)i * 4u, pb + i);                    \
                cp_async4(dst_ + (unsigned)i * 4u, tb + i);                   \
            }                                                                 \
        }                                                                     \
    }                                                                         \
    cp_commit();                                                              \
    iTile += wstride; ipp4 += ptrStep; ipt4 += ptrStep;                       \
} while (0)

    // Prologue: two warp-tiles in flight (slots 0, 1).
    ISSUE(0);
    ISSUE(1);

    // Compute-side carried state.
    int tile = wstart;
    float* outp = out + (size_t)wstart * WTILE + lane;
    const int outStep = wstride * WTILE;

    // STEP(SLOT): wait for this tile, refill slot (SLOT+2)%3, compute+store.
#define STEP(SLOT, ISLOT) do {                                                \
    cp_wait<1>();                                                             \
    __syncwarp();                                                             \
    ISSUE(ISLOT);                                                             \
    {                                                                         \
        const int nb = n - tile * WTILE;                                      \
        const float* spb = sbuf[wid][SLOT][0];                                \
        const float* stb = sbuf[wid][SLOT][1];                                \
        if (lane < nb) {                                                      \
            const float loss = gd_loss_one(                                   \
                spb[b5 + 0], spb[b5 + 1], spb[b5 + 2], spb[b5 + 3], spb[b5 + 4], \
                stb[b5 + 0], stb[b5 + 1], stb[b5 + 2], stb[b5 + 3], stb[b5 + 4]); \
            __stcs(outp, loss);                                               \
        }                                                                     \
    }                                                                         \
    tile += wstride; outp += outStep;                                         \
} while (0)

    for (;;) {
        STEP(0, 2); if (tile >= numTiles) break;
        STEP(1, 0); if (tile >= numTiles) break;
        STEP(2, 1); if (tile >= numTiles) break;
    }

#undef STEP
#undef ISSUE
}

extern "C" void kernel_launch(void* const* d_in, const int* in_sizes, int n_in,
                              void* d_out, int out_size)
{
    const float* pred   = (const float*)d_in[0];
    const float* target = (const float*)d_in[1];
    // d_in[2] (weight) is unused by the reference computation (LOSS_WEIGHT=1).
    float* out = (float*)d_out;

    const int n = out_size;                        // N boxes; output [N,1] floats
    const int numTiles = (n + WTILE - 1) / WTILE;  // 125000 for N=4M
    int grid = GRID_P;
    const int maxGrid = (numTiles + NW - 1) / NW;
    if (grid > maxGrid) grid = maxGrid;
    gd_loss_kernel<<<grid, BLK>>>(pred, target, out, n);
}